// round 15
// baseline (speedup 1.0000x reference)
#include <cuda_runtime.h>

#define BB   256
#define TT   2048
#define INP  29
#define HH   64
#define GG   192   // 3*H
#define NN2  384   // both directions
#define OUTD 11
#define RR   4     // batch rows per recurrence CTA
#define MT   ((size_t)BB * TT)

// Scratch (device globals — no allocation allowed)
__device__ float g_out0[(size_t)BB * TT * 2 * HH];   // [B*T][128] layer-0 bi output
__device__ float g_gx0[(size_t)BB * TT * NN2];       // [B*T][384] layer-0 input gates
__device__ float g_gx1[(size_t)BB * TT * NN2];       // [B*T][384] layer-1 input gates
__device__ float g_hT[BB * 2 * HH];                  // [B][128] final states of layer 1
__device__ float g_Wt0[32 * NN2];                    // transposed layer-0 Wih (padded K=32)
__device__ float g_Wt1[128 * NN2];                   // transposed layer-1 Wih
__device__ float g_xpad[MT * 32];                    // x padded 29 -> 32 cols

// ---------------------------------------------------------------------------
// f32x2 packed helpers (Blackwell FFMA2 — 2x fp32 FMA throughput)
// ---------------------------------------------------------------------------
__device__ __forceinline__ void fma2(unsigned long long& acc,
                                     unsigned long long a, unsigned long long b) {
    asm("fma.rn.f32x2 %0, %1, %2, %0;" : "+l"(acc) : "l"(a), "l"(b));
}
__device__ __forceinline__ unsigned long long dup2(float f) {
    unsigned long long d;
    unsigned int u = __float_as_uint(f);
    asm("mov.b64 %0, {%1, %1};" : "=l"(d) : "r"(u));
    return d;
}
__device__ __forceinline__ float2 unpk(unsigned long long v) {
    unsigned int a, b;
    asm("mov.b64 {%0, %1}, %2;" : "=r"(a), "=r"(b) : "l"(v));
    float2 r; r.x = __uint_as_float(a); r.y = __uint_as_float(b);
    return r;
}

// Clamp-free fast activations (safe at +/-inf by construction).
__device__ __forceinline__ float sigf(float v) {
    float e = __expf(-v);
    return __fdividef(1.f, 1.f + e);
}
__device__ __forceinline__ float tanh_f(float v) {
    float e = __expf(-2.f * v);
    return __fdividef(2.f, 1.f + e) - 1.f;
}

// ---------------------------------------------------------------------------
// One-time W transpose: Wt[k][384] (zero-padded in k), coalesced writes.
// ---------------------------------------------------------------------------
__global__ void transpose_w_kernel(const float* __restrict__ Wf,
                                   const float* __restrict__ Wb,
                                   float* __restrict__ Wt,
                                   int K, int KREAL)
{
    int idx = blockIdx.x * 256 + threadIdx.x;
    if (idx >= K * NN2) return;
    int n = idx % NN2, k = idx / NN2;
    const float* W = (n < GG) ? Wf : Wb;
    int nn = (n < GG) ? n : n - GG;
    Wt[(size_t)k * NN2 + n] = (k < KREAL) ? W[nn * KREAL + k] : 0.f;
}

// ---------------------------------------------------------------------------
// One-time x pad: [B*T][29] -> [B*T][32] (zeros in k>=29).
// ---------------------------------------------------------------------------
__global__ void pad_x_kernel(const float* __restrict__ x, float* __restrict__ xp)
{
    size_t idx = (size_t)blockIdx.x * 256 + threadIdx.x;
    if (idx >= MT * 32) return;
    int k = (int)(idx & 31);
    size_t m = idx >> 5;
    xp[idx] = (k < INP) ? x[m * INP + k] : 0.f;
}

// ---------------------------------------------------------------------------
// Input-gate GEMM v5: gx[m][384] = A[m][KK] @ Wt[KK][384] + bcat
//   CTA tile 128M x 64N, **128 threads**, thread tile 8M x 8N.
//   smem bytes/MAC = 1.0 (vs 1.5 in R7) -> crossbar 64 cyc/k = FFMA2 64 cyc/k.
//   smem 96KB @K=128 -> occ 2;  24KB @K=32 -> occ 3.
//   Single-pass K (R6 lesson); grid n-fastest (R7 lesson); occ>=2 (R11 lesson).
// ---------------------------------------------------------------------------
template<int KK, int MINB>
__global__ void __launch_bounds__(128, MINB) gemm_gx_kernel(
    const float* __restrict__ A, int lda,
    const float* __restrict__ Wt,
    const float* __restrict__ bf, const float* __restrict__ bb,
    float* __restrict__ gx)
{
    extern __shared__ float sm[];
    float* xT = sm;               // [KK][128]
    float* ws = sm + KK * 128;    // [KK][64]

    const int tid = threadIdx.x;
    const int n0g = blockIdx.x * 64;
    const int m0g = blockIdx.y * 128;

    // vectorized A-tile load (lda == KK via pad_x / out0 layout)
#pragma unroll
    for (int it = 0; it < 128 * (KK / 4) / 128; it++) {
        int idx = tid + it * 128;
        int m = idx % 128, k4 = idx / 128;
        float4 v = *(const float4*)&A[(size_t)(m0g + m) * lda + k4 * 4];
        xT[(k4 * 4 + 0) * 128 + m] = v.x;
        xT[(k4 * 4 + 1) * 128 + m] = v.y;
        xT[(k4 * 4 + 2) * 128 + m] = v.z;
        xT[(k4 * 4 + 3) * 128 + m] = v.w;
    }
    // coalesced W tile load: KK x 16 float4s
#pragma unroll
    for (int it = 0; it < KK * 16 / 128; it++) {
        int idx = tid + it * 128;
        int n4 = idx % 16, k = idx / 16;
        *(float4*)&ws[k * 64 + n4 * 4] =
            *(const float4*)&Wt[(size_t)k * NN2 + n0g + n4 * 4];
    }
    __syncthreads();

    const int ty = tid / 8, tx = tid % 8;        // 16 m-groups x 8 n-groups
    const int m0 = ty * 8, n0 = tx * 8;

    unsigned long long acc[8][4];                 // [n][m-pair]
#pragma unroll
    for (int j = 0; j < 8; j++)
#pragma unroll
        for (int p = 0; p < 4; p++) acc[j][p] = 0ull;

#pragma unroll 4
    for (int k = 0; k < KK; k++) {
        ulonglong2 xa = *(const ulonglong2*)&xT[k * 128 + m0];
        ulonglong2 xb = *(const ulonglong2*)&xT[k * 128 + m0 + 4];
        float4 wv0 = *(const float4*)&ws[k * 64 + n0];
        float4 wv1 = *(const float4*)&ws[k * 64 + n0 + 4];
        unsigned long long w0 = dup2(wv0.x), w1 = dup2(wv0.y),
                           w2 = dup2(wv0.z), w3 = dup2(wv0.w);
        unsigned long long w4 = dup2(wv1.x), w5 = dup2(wv1.y),
                           w6 = dup2(wv1.z), w7 = dup2(wv1.w);
        fma2(acc[0][0], w0, xa.x); fma2(acc[0][1], w0, xa.y);
        fma2(acc[0][2], w0, xb.x); fma2(acc[0][3], w0, xb.y);
        fma2(acc[1][0], w1, xa.x); fma2(acc[1][1], w1, xa.y);
        fma2(acc[1][2], w1, xb.x); fma2(acc[1][3], w1, xb.y);
        fma2(acc[2][0], w2, xa.x); fma2(acc[2][1], w2, xa.y);
        fma2(acc[2][2], w2, xb.x); fma2(acc[2][3], w2, xb.y);
        fma2(acc[3][0], w3, xa.x); fma2(acc[3][1], w3, xa.y);
        fma2(acc[3][2], w3, xb.x); fma2(acc[3][3], w3, xb.y);
        fma2(acc[4][0], w4, xa.x); fma2(acc[4][1], w4, xa.y);
        fma2(acc[4][2], w4, xb.x); fma2(acc[4][3], w4, xb.y);
        fma2(acc[5][0], w5, xa.x); fma2(acc[5][1], w5, xa.y);
        fma2(acc[5][2], w5, xb.x); fma2(acc[5][3], w5, xb.y);
        fma2(acc[6][0], w6, xa.x); fma2(acc[6][1], w6, xa.y);
        fma2(acc[6][2], w6, xb.x); fma2(acc[6][3], w6, xb.y);
        fma2(acc[7][0], w7, xa.x); fma2(acc[7][1], w7, xa.y);
        fma2(acc[7][2], w7, xb.x); fma2(acc[7][3], w7, xb.y);
    }

    // ---- epilogue: +bias, two float4 stores per m row ----
    float bias[8];
#pragma unroll
    for (int j = 0; j < 8; j++) {
        int ng = n0g + n0 + j;
        bias[j] = (ng < GG) ? bf[ng] : bb[ng - GG];
    }
    float2 u[8][4];
#pragma unroll
    for (int j = 0; j < 8; j++)
#pragma unroll
        for (int p = 0; p < 4; p++) u[j][p] = unpk(acc[j][p]);

#pragma unroll
    for (int i = 0; i < 8; i++) {
        int p = i >> 1, h = i & 1;
        float4 o0, o1;
        o0.x = (h ? u[0][p].y : u[0][p].x) + bias[0];
        o0.y = (h ? u[1][p].y : u[1][p].x) + bias[1];
        o0.z = (h ? u[2][p].y : u[2][p].x) + bias[2];
        o0.w = (h ? u[3][p].y : u[3][p].x) + bias[3];
        o1.x = (h ? u[4][p].y : u[4][p].x) + bias[4];
        o1.y = (h ? u[5][p].y : u[5][p].x) + bias[5];
        o1.z = (h ? u[6][p].y : u[6][p].x) + bias[6];
        o1.w = (h ? u[7][p].y : u[7][p].x) + bias[7];
        size_t m = (size_t)(m0g + m0 + i);
        *(float4*)&gx[m * NN2 + n0g + n0]     = o0;
        *(float4*)&gx[m * NN2 + n0g + n0 + 4] = o1;
    }
}

// ---------------------------------------------------------------------------
// Recurrence v4 (best measured: 1.14ms/layer — UNCHANGED):
//   384 threads = 12 warps, RR=4 rows, 1 CTA/SM.
// ---------------------------------------------------------------------------
#define RBD 384
__global__ void __launch_bounds__(RBD, 1) rec_kernel(
    const float* __restrict__ gx,
    const float* __restrict__ Whh_f, const float* __restrict__ bhh_f,
    const float* __restrict__ Whh_b, const float* __restrict__ bhh_b,
    float* __restrict__ out_seq,
    float* __restrict__ hT)
{
    const int dir = blockIdx.y;
    const int b0  = blockIdx.x * RR;
    const int tid = threadIdx.x;
    const int j2  = tid % 96;
    const int seg = tid / 96;

    const float* Whh = dir ? Whh_b : Whh_f;
    const float* bhh = dir ? bhh_b : bhh_f;

    unsigned long long whp[2][16];
#pragma unroll
    for (int jj = 0; jj < 2; jj++)
#pragma unroll
        for (int c = 0; c < 16; c++)
            whp[jj][c] = dup2(Whh[(j2 * 2 + jj) * HH + seg * 16 + c]);

    __shared__ __align__(16) float h_sm[HH * RR];
    __shared__ __align__(8)  float x_sm[2][RR][GG];
    __shared__ __align__(8)  float P_sm[4][RR][GG];

    for (int e = tid; e < HH * RR; e += RBD) h_sm[e] = 0.f;

    const int gr = tid >> 6, gk = tid & 63;
    float h_reg = 0.f, bhr = 0.f, bhz = 0.f, bhn = 0.f;
    if (tid < RR * HH) {
        bhr = bhh[gk];
        bhz = bhh[64 + gk];
        bhn = bhh[128 + gk];
    }

    const int tstep = dir ? -1 : 1;
    int t = dir ? (TT - 1) : 0;

    const int pe = tid * 2;
    const int pr = pe / GG, pg = pe % GG;
    const size_t pbase = ((size_t)(b0 + pr) * TT) * NN2 + (size_t)dir * GG + pg;

    *(float2*)&x_sm[0][pr][pg] = *(const float2*)&gx[pbase + (size_t)t * NN2];
    float2 pf_next = (TT > 1) ? *(const float2*)&gx[pbase + (size_t)(t + tstep) * NN2]
                              : make_float2(0.f, 0.f);
    __syncthreads();

    for (int s = 0; s < TT; s++, t += tstep) {
        const int cur = s & 1;

        float2 pf_next2 = make_float2(0.f, 0.f);
        if (s + 2 < TT)
            pf_next2 = *(const float2*)&gx[pbase + (size_t)(t + 2 * tstep) * NN2];

        unsigned long long a0_01 = 0ull, a0_23 = 0ull;
        unsigned long long a1_01 = 0ull, a1_23 = 0ull;
#pragma unroll
        for (int c = 0; c < 16; c++) {
            ulonglong2 h4 = *(const ulonglong2*)&h_sm[(seg * 16 + c) * 4];
            fma2(a0_01, whp[0][c], h4.x);
            fma2(a0_23, whp[0][c], h4.y);
            fma2(a1_01, whp[1][c], h4.x);
            fma2(a1_23, whp[1][c], h4.y);
        }
        {
            float2 v0a = unpk(a0_01), v0b = unpk(a0_23);
            float2 v1a = unpk(a1_01), v1b = unpk(a1_23);
            const int j0 = j2 * 2;
            *(float2*)&P_sm[seg][0][j0] = make_float2(v0a.x, v1a.x);
            *(float2*)&P_sm[seg][1][j0] = make_float2(v0a.y, v1a.y);
            *(float2*)&P_sm[seg][2][j0] = make_float2(v0b.x, v1b.x);
            *(float2*)&P_sm[seg][3][j0] = make_float2(v0b.y, v1b.y);
        }

        if (s + 1 < TT) *(float2*)&x_sm[cur ^ 1][pr][pg] = pf_next;
        pf_next = pf_next2;
        __syncthreads();

        if (tid < RR * HH) {
            float hr = P_sm[0][gr][gk]       + P_sm[1][gr][gk]
                     + P_sm[2][gr][gk]       + P_sm[3][gr][gk]       + bhr;
            float hz = P_sm[0][gr][64 + gk]  + P_sm[1][gr][64 + gk]
                     + P_sm[2][gr][64 + gk]  + P_sm[3][gr][64 + gk]  + bhz;
            float hn = P_sm[0][gr][128 + gk] + P_sm[1][gr][128 + gk]
                     + P_sm[2][gr][128 + gk] + P_sm[3][gr][128 + gk] + bhn;
            float rg = sigf(x_sm[cur][gr][gk]       + hr);
            float zg = sigf(x_sm[cur][gr][64 + gk]  + hz);
            float ng = tanh_f(x_sm[cur][gr][128 + gk] + rg * hn);
            h_reg = (1.f - zg) * ng + zg * h_reg;
            h_sm[gk * 4 + gr] = h_reg;
            if (out_seq)
                out_seq[((size_t)(b0 + gr) * TT + t) * 128 + dir * HH + gk] = h_reg;
        }
        __syncthreads();
    }

    if (hT && tid < RR * HH)
        hT[(b0 + gr) * 128 + dir * HH + gk] = h_reg;
}

// ---------------------------------------------------------------------------
// Head: LayerNorm(128) -> Linear(128->64)+ReLU -> Linear(64->11)
// ---------------------------------------------------------------------------
__global__ void __launch_bounds__(128, 4) head_kernel(
    const float* __restrict__ ln_g, const float* __restrict__ ln_b,
    const float* __restrict__ W1, const float* __restrict__ b1,
    const float* __restrict__ W2, const float* __restrict__ b2,
    float* __restrict__ out)
{
    const int b = blockIdx.x;
    const int tid = threadIdx.x;
    const int lane = tid & 31, wid = tid >> 5;

    __shared__ float y_sm[128];
    __shared__ float h_sm[HH];
    __shared__ float r1[4], r2[4];
    __shared__ float stats[2];

    float e = g_hT[b * 128 + tid];
    float s1 = e, s2 = e * e;
#pragma unroll
    for (int o = 16; o; o >>= 1) {
        s1 += __shfl_down_sync(0xffffffffu, s1, o);
        s2 += __shfl_down_sync(0xffffffffu, s2, o);
    }
    if (lane == 0) { r1[wid] = s1; r2[wid] = s2; }
    __syncthreads();
    if (tid == 0) {
        float a = r1[0] + r1[1] + r1[2] + r1[3];
        float c = r2[0] + r2[1] + r2[2] + r2[3];
        float mu = a * (1.f / 128.f);
        float var = c * (1.f / 128.f) - mu * mu;
        stats[0] = mu;
        stats[1] = rsqrtf(var + 1e-5f);
    }
    __syncthreads();
    y_sm[tid] = (e - stats[0]) * stats[1] * ln_g[tid] + ln_b[tid];
    __syncthreads();

    if (tid < HH) {
        float acc = b1[tid];
#pragma unroll
        for (int kk = 0; kk < 128; kk++) acc += W1[tid * 128 + kk] * y_sm[kk];
        h_sm[tid] = fmaxf(acc, 0.f);
    }
    __syncthreads();
    if (tid < OUTD) {
        float acc = b2[tid];
#pragma unroll
        for (int kk = 0; kk < HH; kk++) acc += W2[tid * HH + kk] * h_sm[kk];
        out[b * OUTD + tid] = acc;
    }
}

// ---------------------------------------------------------------------------
extern "C" void kernel_launch(void* const* d_in, const int* in_sizes, int n_in,
                              void* d_out, int out_size) {
    (void)in_sizes; (void)n_in; (void)out_size;
    const float* x     = (const float*)d_in[0];
    const float* Wih00 = (const float*)d_in[1];
    const float* Whh00 = (const float*)d_in[2];
    const float* bih00 = (const float*)d_in[3];
    const float* bhh00 = (const float*)d_in[4];
    const float* Wih01 = (const float*)d_in[5];
    const float* Whh01 = (const float*)d_in[6];
    const float* bih01 = (const float*)d_in[7];
    const float* bhh01 = (const float*)d_in[8];
    const float* Wih10 = (const float*)d_in[9];
    const float* Whh10 = (const float*)d_in[10];
    const float* bih10 = (const float*)d_in[11];
    const float* bhh10 = (const float*)d_in[12];
    const float* Wih11 = (const float*)d_in[13];
    const float* Whh11 = (const float*)d_in[14];
    const float* bih11 = (const float*)d_in[15];
    const float* bhh11 = (const float*)d_in[16];
    const float* ln_g  = (const float*)d_in[17];
    const float* ln_b  = (const float*)d_in[18];
    const float* W1    = (const float*)d_in[19];
    const float* b1    = (const float*)d_in[20];
    const float* W2    = (const float*)d_in[21];
    const float* b2    = (const float*)d_in[22];
    float* out = (float*)d_out;

    float* gx0  = nullptr; cudaGetSymbolAddress((void**)&gx0,  g_gx0);
    float* gx1  = nullptr; cudaGetSymbolAddress((void**)&gx1,  g_gx1);
    float* out0 = nullptr; cudaGetSymbolAddress((void**)&out0, g_out0);
    float* hT   = nullptr; cudaGetSymbolAddress((void**)&hT,   g_hT);
    float* Wt0  = nullptr; cudaGetSymbolAddress((void**)&Wt0,  g_Wt0);
    float* Wt1  = nullptr; cudaGetSymbolAddress((void**)&Wt1,  g_Wt1);
    float* xpad = nullptr; cudaGetSymbolAddress((void**)&xpad, g_xpad);

    const int smem32  = (32 * 128 + 32 * 64) * 4;     // 24 KB -> occ 3
    const int smem128 = (128 * 128 + 128 * 64) * 4;   // 96 KB -> occ 2
    cudaFuncSetAttribute(gemm_gx_kernel<32, 3>,
                         cudaFuncAttributeMaxDynamicSharedMemorySize, smem32);
    cudaFuncSetAttribute(gemm_gx_kernel<128, 2>,
                         cudaFuncAttributeMaxDynamicSharedMemorySize, smem128);

    // one-time prep: W transposes + x pad (tiny/coalesced)
    transpose_w_kernel<<<(32 * NN2 + 255) / 256, 256>>>(Wih00, Wih01, Wt0, 32, INP);
    transpose_w_kernel<<<(128 * NN2 + 255) / 256, 256>>>(Wih10, Wih11, Wt1, 128, 128);
    pad_x_kernel<<<(int)((MT * 32 + 255) / 256), 256>>>(x, xpad);

    dim3 ggrid(6, MT / 128);      // n-tiles fastest -> A tile L2-resident
    dim3 rgrid(BB / RR, 2);

    gemm_gx_kernel<32, 3><<<ggrid, 128, smem32>>>(xpad, 32, Wt0, bih00, bih01, gx0);
    rec_kernel<<<rgrid, RBD>>>(gx0, Whh00, bhh00, Whh01, bhh01, out0, nullptr);
    gemm_gx_kernel<128, 2><<<ggrid, 128, smem128>>>(out0, 128, Wt1, bih10, bih11, gx1);
    rec_kernel<<<rgrid, RBD>>>(gx1, Whh10, bhh10, Whh11, bhh11, nullptr, hT);
    head_kernel<<<BB, 128>>>(ln_g, ln_b, W1, b1, W2, b2, out);
}

// round 16
// speedup vs baseline: 1.0301x; 1.0301x over previous
#include <cuda_runtime.h>

#define BB   256
#define TT   2048
#define INP  29
#define HH   64
#define GG   192   // 3*H
#define NN2  384   // both directions
#define OUTD 11
#define RR   4     // batch rows per recurrence CTA
#define MT   ((size_t)BB * TT)

#define L2E  1.4426950408889634f

// Scratch (device globals — no allocation allowed)
__device__ float g_out0[(size_t)BB * TT * 2 * HH];   // [B*T][128] layer-0 bi output
__device__ float g_gx0[(size_t)BB * TT * NN2];       // [B*T][384] layer-0 input gates (pre-scaled)
__device__ float g_gx1[(size_t)BB * TT * NN2];       // [B*T][384] layer-1 input gates (pre-scaled)
__device__ float g_hT[BB * 2 * HH];                  // [B][128] final states of layer 1
__device__ float g_Wt0[32 * NN2];                    // transposed+scaled layer-0 Wih
__device__ float g_Wt1[128 * NN2];                   // transposed+scaled layer-1 Wih
__device__ float g_xpad[MT * 32];                    // x padded 29 -> 32 cols

// ---------------------------------------------------------------------------
// f32x2 packed helpers (Blackwell FFMA2 — 2x fp32 FMA throughput)
// ---------------------------------------------------------------------------
__device__ __forceinline__ void fma2(unsigned long long& acc,
                                     unsigned long long a, unsigned long long b) {
    asm("fma.rn.f32x2 %0, %1, %2, %0;" : "+l"(acc) : "l"(a), "l"(b));
}
__device__ __forceinline__ unsigned long long dup2(float f) {
    unsigned long long d;
    unsigned int u = __float_as_uint(f);
    asm("mov.b64 %0, {%1, %1};" : "=l"(d) : "r"(u));
    return d;
}
__device__ __forceinline__ float2 unpk(unsigned long long v) {
    unsigned int a, b;
    asm("mov.b64 {%0, %1}, %2;" : "=r"(a), "=r"(b) : "l"(v));
    float2 r; r.x = __uint_as_float(a); r.y = __uint_as_float(b);
    return r;
}
__device__ __forceinline__ float ex2f(float x) {
    float r;
    asm("ex2.approx.f32 %0, %1;" : "=f"(r) : "f"(x));
    return r;
}

// ---------------------------------------------------------------------------
// Per-gate-row scale: rows [0,128) (r,z gates) get -log2e; rows [128,192)
// (n gate) get -2*log2e. Pre-activations then feed ex2.approx directly:
//   sigmoid(v) = 1/(1+exp(-v)) = 1/(1+ex2(s*v)) with s=-L2E
//   tanh(u)    = 2/(1+exp(-2u))-1 = 2/(1+ex2(s*u))-1 with s=-2*L2E
// ---------------------------------------------------------------------------
__device__ __forceinline__ float gate_scale(int row_in_gg) {
    return (row_in_gg < 2 * HH) ? -L2E : (-2.f * L2E);
}

// ---------------------------------------------------------------------------
// One-time W transpose (+ gate scaling): Wt[k][384], zero-padded in k.
// ---------------------------------------------------------------------------
__global__ void transpose_w_kernel(const float* __restrict__ Wf,
                                   const float* __restrict__ Wb,
                                   float* __restrict__ Wt,
                                   int K, int KREAL)
{
    int idx = blockIdx.x * 256 + threadIdx.x;
    if (idx >= K * NN2) return;
    int n = idx % NN2, k = idx / NN2;
    const float* W = (n < GG) ? Wf : Wb;
    int nn = (n < GG) ? n : n - GG;
    float s = gate_scale(nn);
    Wt[(size_t)k * NN2 + n] = (k < KREAL) ? W[nn * KREAL + k] * s : 0.f;
}

// ---------------------------------------------------------------------------
// One-time x pad: [B*T][29] -> [B*T][32] (zeros in k>=29).
// ---------------------------------------------------------------------------
__global__ void pad_x_kernel(const float* __restrict__ x, float* __restrict__ xp)
{
    size_t idx = (size_t)blockIdx.x * 256 + threadIdx.x;
    if (idx >= MT * 32) return;
    int k = (int)(idx & 31);
    size_t m = idx >> 5;
    xp[idx] = (k < INP) ? x[m * INP + k] : 0.f;
}

// ---------------------------------------------------------------------------
// Input-gate GEMM (R7/R14 structure — measured best):
//   gx[m][384] = A[m][KK] @ Wt[KK][384] + bcat*scale
//   CTA tile 128M x 64N, 256 threads, thread tile 8M x 4N via f32x2 M-pairs.
// ---------------------------------------------------------------------------
template<int KK, int MINB>
__global__ void __launch_bounds__(256, MINB) gemm_gx_kernel(
    const float* __restrict__ A, int lda,
    const float* __restrict__ Wt,
    const float* __restrict__ bf, const float* __restrict__ bb,
    float* __restrict__ gx)
{
    extern __shared__ float sm[];
    float* xT = sm;               // [KK][128]
    float* ws = sm + KK * 128;    // [KK][64]

    const int tid = threadIdx.x;
    const int n0g = blockIdx.x * 64;
    const int m0g = blockIdx.y * 128;

#pragma unroll
    for (int it = 0; it < 128 * (KK / 4) / 256; it++) {
        int idx = tid + it * 256;
        int m = idx % 128, k4 = idx / 128;
        float4 v = *(const float4*)&A[(size_t)(m0g + m) * lda + k4 * 4];
        xT[(k4 * 4 + 0) * 128 + m] = v.x;
        xT[(k4 * 4 + 1) * 128 + m] = v.y;
        xT[(k4 * 4 + 2) * 128 + m] = v.z;
        xT[(k4 * 4 + 3) * 128 + m] = v.w;
    }
#pragma unroll
    for (int it = 0; it < KK * 16 / 256; it++) {
        int idx = tid + it * 256;
        int n4 = idx % 16, k = idx / 16;
        *(float4*)&ws[k * 64 + n4 * 4] =
            *(const float4*)&Wt[(size_t)k * NN2 + n0g + n4 * 4];
    }
    __syncthreads();

    const int ty = tid / 16, tx = tid % 16;
    const int m0 = ty * 8, n0 = tx * 4;

    unsigned long long acc[4][4];
#pragma unroll
    for (int j = 0; j < 4; j++)
#pragma unroll
        for (int p = 0; p < 4; p++) acc[j][p] = 0ull;

#pragma unroll 4
    for (int k = 0; k < KK; k++) {
        ulonglong2 xa = *(const ulonglong2*)&xT[k * 128 + m0];
        ulonglong2 xb = *(const ulonglong2*)&xT[k * 128 + m0 + 4];
        float4 wv = *(const float4*)&ws[k * 64 + n0];
        unsigned long long w0 = dup2(wv.x), w1 = dup2(wv.y),
                           w2 = dup2(wv.z), w3 = dup2(wv.w);
        fma2(acc[0][0], w0, xa.x); fma2(acc[0][1], w0, xa.y);
        fma2(acc[0][2], w0, xb.x); fma2(acc[0][3], w0, xb.y);
        fma2(acc[1][0], w1, xa.x); fma2(acc[1][1], w1, xa.y);
        fma2(acc[1][2], w1, xb.x); fma2(acc[1][3], w1, xb.y);
        fma2(acc[2][0], w2, xa.x); fma2(acc[2][1], w2, xa.y);
        fma2(acc[2][2], w2, xb.x); fma2(acc[2][3], w2, xb.y);
        fma2(acc[3][0], w3, xa.x); fma2(acc[3][1], w3, xa.y);
        fma2(acc[3][2], w3, xb.x); fma2(acc[3][3], w3, xb.y);
    }

    float bias[4];
#pragma unroll
    for (int j = 0; j < 4; j++) {
        int ng = n0g + n0 + j;
        int nn = (ng < GG) ? ng : ng - GG;
        float braw = (ng < GG) ? bf[nn] : bb[nn];
        bias[j] = braw * gate_scale(nn);
    }
    float2 u[4][4];
#pragma unroll
    for (int j = 0; j < 4; j++)
#pragma unroll
        for (int p = 0; p < 4; p++) u[j][p] = unpk(acc[j][p]);

#pragma unroll
    for (int i = 0; i < 8; i++) {
        int p = i >> 1, h = i & 1;
        float4 o;
        o.x = (h ? u[0][p].y : u[0][p].x) + bias[0];
        o.y = (h ? u[1][p].y : u[1][p].x) + bias[1];
        o.z = (h ? u[2][p].y : u[2][p].x) + bias[2];
        o.w = (h ? u[3][p].y : u[3][p].x) + bias[3];
        size_t m = (size_t)(m0g + m0 + i);
        *(float4*)&gx[m * NN2 + n0g + n0] = o;
    }
}

// ---------------------------------------------------------------------------
// Recurrence v4 geometry (frozen) + streamlined gate math:
//   weights/biases pre-scaled by gate_scale at register-load time, so the
//   GEMV output feeds ex2.approx directly; shared reciprocal for r/z gates.
//   384 threads = 12 warps, RR=4 rows, 1 CTA/SM.
// ---------------------------------------------------------------------------
#define RBD 384
__global__ void __launch_bounds__(RBD, 1) rec_kernel(
    const float* __restrict__ gx,
    const float* __restrict__ Whh_f, const float* __restrict__ bhh_f,
    const float* __restrict__ Whh_b, const float* __restrict__ bhh_b,
    float* __restrict__ out_seq,
    float* __restrict__ hT)
{
    const int dir = blockIdx.y;
    const int b0  = blockIdx.x * RR;
    const int tid = threadIdx.x;
    const int j2  = tid % 96;
    const int seg = tid / 96;

    const float* Whh = dir ? Whh_b : Whh_f;
    const float* bhh = dir ? bhh_b : bhh_f;

    unsigned long long whp[2][16];
#pragma unroll
    for (int jj = 0; jj < 2; jj++) {
        const int j = j2 * 2 + jj;
        const float s = gate_scale(j);
#pragma unroll
        for (int c = 0; c < 16; c++)
            whp[jj][c] = dup2(Whh[j * HH + seg * 16 + c] * s);
    }

    __shared__ __align__(16) float h_sm[HH * RR];
    __shared__ __align__(8)  float x_sm[2][RR][GG];
    __shared__ __align__(8)  float P_sm[4][RR][GG];

    for (int e = tid; e < HH * RR; e += RBD) h_sm[e] = 0.f;

    const int gr = tid >> 6, gk = tid & 63;
    float h_reg = 0.f, bhr = 0.f, bhz = 0.f, bhn = 0.f;
    if (tid < RR * HH) {
        bhr = bhh[gk]       * (-L2E);
        bhz = bhh[64 + gk]  * (-L2E);
        bhn = bhh[128 + gk] * (-2.f * L2E);
    }

    const int tstep = dir ? -1 : 1;
    int t = dir ? (TT - 1) : 0;

    const int pe = tid * 2;
    const int pr = pe / GG, pg = pe % GG;
    const size_t pbase = ((size_t)(b0 + pr) * TT) * NN2 + (size_t)dir * GG + pg;

    *(float2*)&x_sm[0][pr][pg] = *(const float2*)&gx[pbase + (size_t)t * NN2];
    float2 pf_next = (TT > 1) ? *(const float2*)&gx[pbase + (size_t)(t + tstep) * NN2]
                              : make_float2(0.f, 0.f);
    __syncthreads();

    for (int s = 0; s < TT; s++, t += tstep) {
        const int cur = s & 1;

        float2 pf_next2 = make_float2(0.f, 0.f);
        if (s + 2 < TT)
            pf_next2 = *(const float2*)&gx[pbase + (size_t)(t + 2 * tstep) * NN2];

        unsigned long long a0_01 = 0ull, a0_23 = 0ull;
        unsigned long long a1_01 = 0ull, a1_23 = 0ull;
#pragma unroll
        for (int c = 0; c < 16; c++) {
            ulonglong2 h4 = *(const ulonglong2*)&h_sm[(seg * 16 + c) * 4];
            fma2(a0_01, whp[0][c], h4.x);
            fma2(a0_23, whp[0][c], h4.y);
            fma2(a1_01, whp[1][c], h4.x);
            fma2(a1_23, whp[1][c], h4.y);
        }
        {
            float2 v0a = unpk(a0_01), v0b = unpk(a0_23);
            float2 v1a = unpk(a1_01), v1b = unpk(a1_23);
            const int j0 = j2 * 2;
            *(float2*)&P_sm[seg][0][j0] = make_float2(v0a.x, v1a.x);
            *(float2*)&P_sm[seg][1][j0] = make_float2(v0a.y, v1a.y);
            *(float2*)&P_sm[seg][2][j0] = make_float2(v0b.x, v1b.x);
            *(float2*)&P_sm[seg][3][j0] = make_float2(v0b.y, v1b.y);
        }

        if (s + 1 < TT) *(float2*)&x_sm[cur ^ 1][pr][pg] = pf_next;
        pf_next = pf_next2;
        __syncthreads();

        if (tid < RR * HH) {
            // pre-activations already scaled for direct ex2
            float vr = P_sm[0][gr][gk]       + P_sm[1][gr][gk]
                     + P_sm[2][gr][gk]       + P_sm[3][gr][gk]
                     + bhr + x_sm[cur][gr][gk];
            float vz = P_sm[0][gr][64 + gk]  + P_sm[1][gr][64 + gk]
                     + P_sm[2][gr][64 + gk]  + P_sm[3][gr][64 + gk]
                     + bhz + x_sm[cur][gr][64 + gk];
            float hn = P_sm[0][gr][128 + gk] + P_sm[1][gr][128 + gk]
                     + P_sm[2][gr][128 + gk] + P_sm[3][gr][128 + gk] + bhn;
            float xn = x_sm[cur][gr][128 + gk];

            float e1 = ex2f(vr);               // = exp(-(raw r preact))
            float e2 = ex2f(vz);
            float d1 = 1.f + e1, d2 = 1.f + e2;
            float q  = __fdividef(1.f, d1 * d2);   // one RCP for both sigmoids
            float rg = d2 * q;
            float zg = d1 * q;
            float e3 = ex2f(xn + rg * hn);     // n-channel pre-scaled by -2*L2E
            float ng = __fdividef(2.f, 1.f + e3) - 1.f;
            h_reg = ng + zg * (h_reg - ng);
            h_sm[gk * 4 + gr] = h_reg;
            if (out_seq)
                out_seq[((size_t)(b0 + gr) * TT + t) * 128 + dir * HH + gk] = h_reg;
        }
        __syncthreads();
    }

    if (hT && tid < RR * HH)
        hT[(b0 + gr) * 128 + dir * HH + gk] = h_reg;
}

// ---------------------------------------------------------------------------
// Head: LayerNorm(128) -> Linear(128->64)+ReLU -> Linear(64->11)
// ---------------------------------------------------------------------------
__global__ void __launch_bounds__(128, 4) head_kernel(
    const float* __restrict__ ln_g, const float* __restrict__ ln_b,
    const float* __restrict__ W1, const float* __restrict__ b1,
    const float* __restrict__ W2, const float* __restrict__ b2,
    float* __restrict__ out)
{
    const int b = blockIdx.x;
    const int tid = threadIdx.x;
    const int lane = tid & 31, wid = tid >> 5;

    __shared__ float y_sm[128];
    __shared__ float h_sm[HH];
    __shared__ float r1[4], r2[4];
    __shared__ float stats[2];

    float e = g_hT[b * 128 + tid];
    float s1 = e, s2 = e * e;
#pragma unroll
    for (int o = 16; o; o >>= 1) {
        s1 += __shfl_down_sync(0xffffffffu, s1, o);
        s2 += __shfl_down_sync(0xffffffffu, s2, o);
    }
    if (lane == 0) { r1[wid] = s1; r2[wid] = s2; }
    __syncthreads();
    if (tid == 0) {
        float a = r1[0] + r1[1] + r1[2] + r1[3];
        float c = r2[0] + r2[1] + r2[2] + r2[3];
        float mu = a * (1.f / 128.f);
        float var = c * (1.f / 128.f) - mu * mu;
        stats[0] = mu;
        stats[1] = rsqrtf(var + 1e-5f);
    }
    __syncthreads();
    y_sm[tid] = (e - stats[0]) * stats[1] * ln_g[tid] + ln_b[tid];
    __syncthreads();

    if (tid < HH) {
        float acc = b1[tid];
#pragma unroll
        for (int kk = 0; kk < 128; kk++) acc += W1[tid * 128 + kk] * y_sm[kk];
        h_sm[tid] = fmaxf(acc, 0.f);
    }
    __syncthreads();
    if (tid < OUTD) {
        float acc = b2[tid];
#pragma unroll
        for (int kk = 0; kk < HH; kk++) acc += W2[tid * HH + kk] * h_sm[kk];
        out[b * OUTD + tid] = acc;
    }
}

// ---------------------------------------------------------------------------
extern "C" void kernel_launch(void* const* d_in, const int* in_sizes, int n_in,
                              void* d_out, int out_size) {
    (void)in_sizes; (void)n_in; (void)out_size;
    const float* x     = (const float*)d_in[0];
    const float* Wih00 = (const float*)d_in[1];
    const float* Whh00 = (const float*)d_in[2];
    const float* bih00 = (const float*)d_in[3];
    const float* bhh00 = (const float*)d_in[4];
    const float* Wih01 = (const float*)d_in[5];
    const float* Whh01 = (const float*)d_in[6];
    const float* bih01 = (const float*)d_in[7];
    const float* bhh01 = (const float*)d_in[8];
    const float* Wih10 = (const float*)d_in[9];
    const float* Whh10 = (const float*)d_in[10];
    const float* bih10 = (const float*)d_in[11];
    const float* bhh10 = (const float*)d_in[12];
    const float* Wih11 = (const float*)d_in[13];
    const float* Whh11 = (const float*)d_in[14];
    const float* bih11 = (const float*)d_in[15];
    const float* bhh11 = (const float*)d_in[16];
    const float* ln_g  = (const float*)d_in[17];
    const float* ln_b  = (const float*)d_in[18];
    const float* W1    = (const float*)d_in[19];
    const float* b1    = (const float*)d_in[20];
    const float* W2    = (const float*)d_in[21];
    const float* b2    = (const float*)d_in[22];
    float* out = (float*)d_out;

    float* gx0  = nullptr; cudaGetSymbolAddress((void**)&gx0,  g_gx0);
    float* gx1  = nullptr; cudaGetSymbolAddress((void**)&gx1,  g_gx1);
    float* out0 = nullptr; cudaGetSymbolAddress((void**)&out0, g_out0);
    float* hT   = nullptr; cudaGetSymbolAddress((void**)&hT,   g_hT);
    float* Wt0  = nullptr; cudaGetSymbolAddress((void**)&Wt0,  g_Wt0);
    float* Wt1  = nullptr; cudaGetSymbolAddress((void**)&Wt1,  g_Wt1);
    float* xpad = nullptr; cudaGetSymbolAddress((void**)&xpad, g_xpad);

    const int smem32  = (32 * 128 + 32 * 64) * 4;     // 24 KB -> occ 3
    const int smem128 = (128 * 128 + 128 * 64) * 4;   // 96 KB -> occ 2
    cudaFuncSetAttribute(gemm_gx_kernel<32, 3>,
                         cudaFuncAttributeMaxDynamicSharedMemorySize, smem32);
    cudaFuncSetAttribute(gemm_gx_kernel<128, 2>,
                         cudaFuncAttributeMaxDynamicSharedMemorySize, smem128);

    // one-time prep: scaled W transposes + x pad
    transpose_w_kernel<<<(32 * NN2 + 255) / 256, 256>>>(Wih00, Wih01, Wt0, 32, INP);
    transpose_w_kernel<<<(128 * NN2 + 255) / 256, 256>>>(Wih10, Wih11, Wt1, 128, 128);
    pad_x_kernel<<<(int)((MT * 32 + 255) / 256), 256>>>(x, xpad);

    dim3 ggrid(6, MT / 128);      // n-tiles fastest -> A tile L2-resident
    dim3 rgrid(BB / RR, 2);

    gemm_gx_kernel<32, 3><<<ggrid, 256, smem32>>>(xpad, 32, Wt0, bih00, bih01, gx0);
    rec_kernel<<<rgrid, RBD>>>(gx0, Whh00, bhh00, Whh01, bhh01, out0, nullptr);
    gemm_gx_kernel<128, 2><<<ggrid, 256, smem128>>>(out0, 128, Wt1, bih10, bih11, gx1);
    rec_kernel<<<rgrid, RBD>>>(gx1, Whh10, bhh10, Whh11, bhh11, nullptr, hT);
    head_kernel<<<BB, 128>>>(ln_g, ln_b, W1, b1, W2, b2, out);
}

// round 17
// speedup vs baseline: 1.1227x; 1.0899x over previous
#include <cuda_runtime.h>
#include <cuda_fp16.h>

#define BB   256
#define TT   2048
#define INP  29
#define HH   64
#define GG   192   // 3*H
#define NN2  384   // both directions
#define OUTD 11
#define RR   4     // batch rows per recurrence CTA
#define MT   ((size_t)BB * TT)

#define L2E  1.4426950408889634f

// Scratch (device globals — no allocation allowed). Intermediates in fp16
// (storage only; all compute fp32).
__device__ __half g_out0[(size_t)BB * TT * 2 * HH];  // [B*T][128] layer-0 output
__device__ __half g_gx0[(size_t)BB * TT * NN2];      // [B*T][384] l0 input gates (pre-scaled)
__device__ __half g_gx1[(size_t)BB * TT * NN2];      // [B*T][384] l1 input gates
__device__ float  g_hT[BB * 2 * HH];                 // [B][128] final states (fp32)
__device__ float  g_Wt0[32 * NN2];                   // transposed+scaled layer-0 Wih
__device__ float  g_Wt1[128 * NN2];                  // transposed+scaled layer-1 Wih
__device__ __half g_xpad[MT * 32];                   // x padded 29 -> 32 cols (fp16)

// ---------------------------------------------------------------------------
// f32x2 packed helpers (Blackwell FFMA2 — 2x fp32 FMA throughput)
// ---------------------------------------------------------------------------
__device__ __forceinline__ void fma2(unsigned long long& acc,
                                     unsigned long long a, unsigned long long b) {
    asm("fma.rn.f32x2 %0, %1, %2, %0;" : "+l"(acc) : "l"(a), "l"(b));
}
__device__ __forceinline__ unsigned long long dup2(float f) {
    unsigned long long d;
    unsigned int u = __float_as_uint(f);
    asm("mov.b64 %0, {%1, %1};" : "=l"(d) : "r"(u));
    return d;
}
__device__ __forceinline__ float2 unpk(unsigned long long v) {
    unsigned int a, b;
    asm("mov.b64 {%0, %1}, %2;" : "=r"(a), "=r"(b) : "l"(v));
    float2 r; r.x = __uint_as_float(a); r.y = __uint_as_float(b);
    return r;
}
__device__ __forceinline__ float ex2f(float x) {
    float r;
    asm("ex2.approx.f32 %0, %1;" : "=f"(r) : "f"(x));
    return r;
}

// Per-gate-row scale: r,z rows get -log2e; n rows get -2*log2e (feeds ex2 directly).
__device__ __forceinline__ float gate_scale(int row_in_gg) {
    return (row_in_gg < 2 * HH) ? -L2E : (-2.f * L2E);
}

// ---------------------------------------------------------------------------
// One-time W transpose (+ gate scaling): Wt[k][384], zero-padded in k. fp32.
// ---------------------------------------------------------------------------
__global__ void transpose_w_kernel(const float* __restrict__ Wf,
                                   const float* __restrict__ Wb,
                                   float* __restrict__ Wt,
                                   int K, int KREAL)
{
    int idx = blockIdx.x * 256 + threadIdx.x;
    if (idx >= K * NN2) return;
    int n = idx % NN2, k = idx / NN2;
    const float* W = (n < GG) ? Wf : Wb;
    int nn = (n < GG) ? n : n - GG;
    float s = gate_scale(nn);
    Wt[(size_t)k * NN2 + n] = (k < KREAL) ? W[nn * KREAL + k] * s : 0.f;
}

// ---------------------------------------------------------------------------
// One-time x pad: [B*T][29] fp32 -> [B*T][32] fp16 (zeros in k>=29).
// ---------------------------------------------------------------------------
__global__ void pad_x_kernel(const float* __restrict__ x, __half* __restrict__ xp)
{
    size_t idx = (size_t)blockIdx.x * 256 + threadIdx.x;
    if (idx >= MT * 32) return;
    int k = (int)(idx & 31);
    size_t m = idx >> 5;
    xp[idx] = __float2half((k < INP) ? x[m * INP + k] : 0.f);
}

// ---------------------------------------------------------------------------
// Input-gate GEMM (R7/R16 structure — frozen geometry):
//   gx[m][384] = A_half[m][KK] @ Wt[KK][384] + bcat*scale  (fp32 compute)
//   CTA tile 128M x 64N, 256 threads, thread tile 8M x 4N via f32x2 M-pairs.
//   A read as fp16 (uint4 = 8 halves/thread), gx written as fp16.
// ---------------------------------------------------------------------------
template<int KK, int MINB>
__global__ void __launch_bounds__(256, MINB) gemm_gx_kernel(
    const __half* __restrict__ A, int lda,
    const float* __restrict__ Wt,
    const float* __restrict__ bf, const float* __restrict__ bb,
    __half* __restrict__ gx)
{
    extern __shared__ float sm[];
    float* xT = sm;               // [KK][128]
    float* ws = sm + KK * 128;    // [KK][64]

    const int tid = threadIdx.x;
    const int n0g = blockIdx.x * 64;
    const int m0g = blockIdx.y * 128;

    // A tile (fp16, 8 halves per uint4) -> xT fp32 transposed
#pragma unroll
    for (int it = 0; it < 128 * (KK / 8) / 256; it++) {
        int idx = tid + it * 256;
        int m = idx % 128, k8 = idx / 128;
        uint4 v = *(const uint4*)&A[(size_t)(m0g + m) * lda + k8 * 8];
        float2 f0 = __half22float2(*reinterpret_cast<__half2*>(&v.x));
        float2 f1 = __half22float2(*reinterpret_cast<__half2*>(&v.y));
        float2 f2 = __half22float2(*reinterpret_cast<__half2*>(&v.z));
        float2 f3 = __half22float2(*reinterpret_cast<__half2*>(&v.w));
        xT[(k8 * 8 + 0) * 128 + m] = f0.x;
        xT[(k8 * 8 + 1) * 128 + m] = f0.y;
        xT[(k8 * 8 + 2) * 128 + m] = f1.x;
        xT[(k8 * 8 + 3) * 128 + m] = f1.y;
        xT[(k8 * 8 + 4) * 128 + m] = f2.x;
        xT[(k8 * 8 + 5) * 128 + m] = f2.y;
        xT[(k8 * 8 + 6) * 128 + m] = f3.x;
        xT[(k8 * 8 + 7) * 128 + m] = f3.y;
    }
    // W tile (fp32, coalesced float4)
#pragma unroll
    for (int it = 0; it < KK * 16 / 256; it++) {
        int idx = tid + it * 256;
        int n4 = idx % 16, k = idx / 16;
        *(float4*)&ws[k * 64 + n4 * 4] =
            *(const float4*)&Wt[(size_t)k * NN2 + n0g + n4 * 4];
    }
    __syncthreads();

    const int ty = tid / 16, tx = tid % 16;
    const int m0 = ty * 8, n0 = tx * 4;

    unsigned long long acc[4][4];
#pragma unroll
    for (int j = 0; j < 4; j++)
#pragma unroll
        for (int p = 0; p < 4; p++) acc[j][p] = 0ull;

#pragma unroll 4
    for (int k = 0; k < KK; k++) {
        ulonglong2 xa = *(const ulonglong2*)&xT[k * 128 + m0];
        ulonglong2 xb = *(const ulonglong2*)&xT[k * 128 + m0 + 4];
        float4 wv = *(const float4*)&ws[k * 64 + n0];
        unsigned long long w0 = dup2(wv.x), w1 = dup2(wv.y),
                           w2 = dup2(wv.z), w3 = dup2(wv.w);
        fma2(acc[0][0], w0, xa.x); fma2(acc[0][1], w0, xa.y);
        fma2(acc[0][2], w0, xb.x); fma2(acc[0][3], w0, xb.y);
        fma2(acc[1][0], w1, xa.x); fma2(acc[1][1], w1, xa.y);
        fma2(acc[1][2], w1, xb.x); fma2(acc[1][3], w1, xb.y);
        fma2(acc[2][0], w2, xa.x); fma2(acc[2][1], w2, xa.y);
        fma2(acc[2][2], w2, xb.x); fma2(acc[2][3], w2, xb.y);
        fma2(acc[3][0], w3, xa.x); fma2(acc[3][1], w3, xa.y);
        fma2(acc[3][2], w3, xb.x); fma2(acc[3][3], w3, xb.y);
    }

    float bias[4];
#pragma unroll
    for (int j = 0; j < 4; j++) {
        int ng = n0g + n0 + j;
        int nn = (ng < GG) ? ng : ng - GG;
        float braw = (ng < GG) ? bf[nn] : bb[nn];
        bias[j] = braw * gate_scale(nn);
    }
    float2 u[4][4];
#pragma unroll
    for (int j = 0; j < 4; j++)
#pragma unroll
        for (int p = 0; p < 4; p++) u[j][p] = unpk(acc[j][p]);

#pragma unroll
    for (int i = 0; i < 8; i++) {
        int p = i >> 1, h = i & 1;
        float4 o;
        o.x = (h ? u[0][p].y : u[0][p].x) + bias[0];
        o.y = (h ? u[1][p].y : u[1][p].x) + bias[1];
        o.z = (h ? u[2][p].y : u[2][p].x) + bias[2];
        o.w = (h ? u[3][p].y : u[3][p].x) + bias[3];
        __half2 lo = __floats2half2_rn(o.x, o.y);
        __half2 hi = __floats2half2_rn(o.z, o.w);
        uint2 st;
        st.x = *reinterpret_cast<unsigned int*>(&lo);
        st.y = *reinterpret_cast<unsigned int*>(&hi);
        size_t m = (size_t)(m0g + m0 + i);
        *(uint2*)&gx[m * NN2 + n0g + n0] = st;
    }
}

// ---------------------------------------------------------------------------
// Recurrence v4 geometry (frozen) + R16 gate math. gx read as fp16 (half2
// prefetch, converted to fp32 at the smem store); out_seq written fp16.
//   384 threads = 12 warps, RR=4 rows, 1 CTA/SM.
// ---------------------------------------------------------------------------
#define RBD 384
__global__ void __launch_bounds__(RBD, 1) rec_kernel(
    const __half* __restrict__ gx,
    const float* __restrict__ Whh_f, const float* __restrict__ bhh_f,
    const float* __restrict__ Whh_b, const float* __restrict__ bhh_b,
    __half* __restrict__ out_seq,
    float* __restrict__ hT)
{
    const int dir = blockIdx.y;
    const int b0  = blockIdx.x * RR;
    const int tid = threadIdx.x;
    const int j2  = tid % 96;
    const int seg = tid / 96;

    const float* Whh = dir ? Whh_b : Whh_f;
    const float* bhh = dir ? bhh_b : bhh_f;

    unsigned long long whp[2][16];
#pragma unroll
    for (int jj = 0; jj < 2; jj++) {
        const int j = j2 * 2 + jj;
        const float s = gate_scale(j);
#pragma unroll
        for (int c = 0; c < 16; c++)
            whp[jj][c] = dup2(Whh[j * HH + seg * 16 + c] * s);
    }

    __shared__ __align__(16) float h_sm[HH * RR];
    __shared__ __align__(8)  float x_sm[2][RR][GG];
    __shared__ __align__(8)  float P_sm[4][RR][GG];

    for (int e = tid; e < HH * RR; e += RBD) h_sm[e] = 0.f;

    const int gr = tid >> 6, gk = tid & 63;
    float h_reg = 0.f, bhr = 0.f, bhz = 0.f, bhn = 0.f;
    if (tid < RR * HH) {
        bhr = bhh[gk]       * (-L2E);
        bhz = bhh[64 + gk]  * (-L2E);
        bhn = bhh[128 + gk] * (-2.f * L2E);
    }

    const int tstep = dir ? -1 : 1;
    int t = dir ? (TT - 1) : 0;

    const int pe = tid * 2;
    const int pr = pe / GG, pg = pe % GG;
    const size_t pbase = ((size_t)(b0 + pr) * TT) * NN2 + (size_t)dir * GG + pg;

    *(float2*)&x_sm[0][pr][pg] =
        __half22float2(*(const __half2*)&gx[pbase + (size_t)t * NN2]);
    __half2 pf_next = __floats2half2_rn(0.f, 0.f);
    if (TT > 1)
        pf_next = *(const __half2*)&gx[pbase + (size_t)(t + tstep) * NN2];
    __syncthreads();

    for (int s = 0; s < TT; s++, t += tstep) {
        const int cur = s & 1;

        __half2 pf_next2 = __floats2half2_rn(0.f, 0.f);
        if (s + 2 < TT)
            pf_next2 = *(const __half2*)&gx[pbase + (size_t)(t + 2 * tstep) * NN2];

        unsigned long long a0_01 = 0ull, a0_23 = 0ull;
        unsigned long long a1_01 = 0ull, a1_23 = 0ull;
#pragma unroll
        for (int c = 0; c < 16; c++) {
            ulonglong2 h4 = *(const ulonglong2*)&h_sm[(seg * 16 + c) * 4];
            fma2(a0_01, whp[0][c], h4.x);
            fma2(a0_23, whp[0][c], h4.y);
            fma2(a1_01, whp[1][c], h4.x);
            fma2(a1_23, whp[1][c], h4.y);
        }
        {
            float2 v0a = unpk(a0_01), v0b = unpk(a0_23);
            float2 v1a = unpk(a1_01), v1b = unpk(a1_23);
            const int j0 = j2 * 2;
            *(float2*)&P_sm[seg][0][j0] = make_float2(v0a.x, v1a.x);
            *(float2*)&P_sm[seg][1][j0] = make_float2(v0a.y, v1a.y);
            *(float2*)&P_sm[seg][2][j0] = make_float2(v0b.x, v1b.x);
            *(float2*)&P_sm[seg][3][j0] = make_float2(v0b.y, v1b.y);
        }

        if (s + 1 < TT)
            *(float2*)&x_sm[cur ^ 1][pr][pg] = __half22float2(pf_next);
        pf_next = pf_next2;
        __syncthreads();

        if (tid < RR * HH) {
            float vr = P_sm[0][gr][gk]       + P_sm[1][gr][gk]
                     + P_sm[2][gr][gk]       + P_sm[3][gr][gk]
                     + bhr + x_sm[cur][gr][gk];
            float vz = P_sm[0][gr][64 + gk]  + P_sm[1][gr][64 + gk]
                     + P_sm[2][gr][64 + gk]  + P_sm[3][gr][64 + gk]
                     + bhz + x_sm[cur][gr][64 + gk];
            float hn = P_sm[0][gr][128 + gk] + P_sm[1][gr][128 + gk]
                     + P_sm[2][gr][128 + gk] + P_sm[3][gr][128 + gk] + bhn;
            float xn = x_sm[cur][gr][128 + gk];

            float e1 = ex2f(vr);
            float e2 = ex2f(vz);
            float d1 = 1.f + e1, d2 = 1.f + e2;
            float q  = __fdividef(1.f, d1 * d2);
            float rg = d2 * q;
            float zg = d1 * q;
            float e3 = ex2f(xn + rg * hn);
            float ng = __fdividef(2.f, 1.f + e3) - 1.f;
            h_reg = ng + zg * (h_reg - ng);
            h_sm[gk * 4 + gr] = h_reg;
            if (out_seq)
                out_seq[((size_t)(b0 + gr) * TT + t) * 128 + dir * HH + gk] =
                    __float2half(h_reg);
        }
        __syncthreads();
    }

    if (hT && tid < RR * HH)
        hT[(b0 + gr) * 128 + dir * HH + gk] = h_reg;
}

// ---------------------------------------------------------------------------
// Head: LayerNorm(128) -> Linear(128->64)+ReLU -> Linear(64->11)
// ---------------------------------------------------------------------------
__global__ void __launch_bounds__(128, 4) head_kernel(
    const float* __restrict__ ln_g, const float* __restrict__ ln_b,
    const float* __restrict__ W1, const float* __restrict__ b1,
    const float* __restrict__ W2, const float* __restrict__ b2,
    float* __restrict__ out)
{
    const int b = blockIdx.x;
    const int tid = threadIdx.x;
    const int lane = tid & 31, wid = tid >> 5;

    __shared__ float y_sm[128];
    __shared__ float h_sm[HH];
    __shared__ float r1[4], r2[4];
    __shared__ float stats[2];

    float e = g_hT[b * 128 + tid];
    float s1 = e, s2 = e * e;
#pragma unroll
    for (int o = 16; o; o >>= 1) {
        s1 += __shfl_down_sync(0xffffffffu, s1, o);
        s2 += __shfl_down_sync(0xffffffffu, s2, o);
    }
    if (lane == 0) { r1[wid] = s1; r2[wid] = s2; }
    __syncthreads();
    if (tid == 0) {
        float a = r1[0] + r1[1] + r1[2] + r1[3];
        float c = r2[0] + r2[1] + r2[2] + r2[3];
        float mu = a * (1.f / 128.f);
        float var = c * (1.f / 128.f) - mu * mu;
        stats[0] = mu;
        stats[1] = rsqrtf(var + 1e-5f);
    }
    __syncthreads();
    y_sm[tid] = (e - stats[0]) * stats[1] * ln_g[tid] + ln_b[tid];
    __syncthreads();

    if (tid < HH) {
        float acc = b1[tid];
#pragma unroll
        for (int kk = 0; kk < 128; kk++) acc += W1[tid * 128 + kk] * y_sm[kk];
        h_sm[tid] = fmaxf(acc, 0.f);
    }
    __syncthreads();
    if (tid < OUTD) {
        float acc = b2[tid];
#pragma unroll
        for (int kk = 0; kk < HH; kk++) acc += W2[tid * HH + kk] * h_sm[kk];
        out[b * OUTD + tid] = acc;
    }
}

// ---------------------------------------------------------------------------
extern "C" void kernel_launch(void* const* d_in, const int* in_sizes, int n_in,
                              void* d_out, int out_size) {
    (void)in_sizes; (void)n_in; (void)out_size;
    const float* x     = (const float*)d_in[0];
    const float* Wih00 = (const float*)d_in[1];
    const float* Whh00 = (const float*)d_in[2];
    const float* bih00 = (const float*)d_in[3];
    const float* bhh00 = (const float*)d_in[4];
    const float* Wih01 = (const float*)d_in[5];
    const float* Whh01 = (const float*)d_in[6];
    const float* bih01 = (const float*)d_in[7];
    const float* bhh01 = (const float*)d_in[8];
    const float* Wih10 = (const float*)d_in[9];
    const float* Whh10 = (const float*)d_in[10];
    const float* bih10 = (const float*)d_in[11];
    const float* bhh10 = (const float*)d_in[12];
    const float* Wih11 = (const float*)d_in[13];
    const float* Whh11 = (const float*)d_in[14];
    const float* bih11 = (const float*)d_in[15];
    const float* bhh11 = (const float*)d_in[16];
    const float* ln_g  = (const float*)d_in[17];
    const float* ln_b  = (const float*)d_in[18];
    const float* W1    = (const float*)d_in[19];
    const float* b1    = (const float*)d_in[20];
    const float* W2    = (const float*)d_in[21];
    const float* b2    = (const float*)d_in[22];
    float* out = (float*)d_out;

    __half* gx0  = nullptr; cudaGetSymbolAddress((void**)&gx0,  g_gx0);
    __half* gx1  = nullptr; cudaGetSymbolAddress((void**)&gx1,  g_gx1);
    __half* out0 = nullptr; cudaGetSymbolAddress((void**)&out0, g_out0);
    float*  hT   = nullptr; cudaGetSymbolAddress((void**)&hT,   g_hT);
    float*  Wt0  = nullptr; cudaGetSymbolAddress((void**)&Wt0,  g_Wt0);
    float*  Wt1  = nullptr; cudaGetSymbolAddress((void**)&Wt1,  g_Wt1);
    __half* xpad = nullptr; cudaGetSymbolAddress((void**)&xpad, g_xpad);

    const int smem32  = (32 * 128 + 32 * 64) * 4;     // 24 KB -> occ 3
    const int smem128 = (128 * 128 + 128 * 64) * 4;   // 96 KB -> occ 2
    cudaFuncSetAttribute(gemm_gx_kernel<32, 3>,
                         cudaFuncAttributeMaxDynamicSharedMemorySize, smem32);
    cudaFuncSetAttribute(gemm_gx_kernel<128, 2>,
                         cudaFuncAttributeMaxDynamicSharedMemorySize, smem128);

    // one-time prep: scaled W transposes + x pad
    transpose_w_kernel<<<(32 * NN2 + 255) / 256, 256>>>(Wih00, Wih01, Wt0, 32, INP);
    transpose_w_kernel<<<(128 * NN2 + 255) / 256, 256>>>(Wih10, Wih11, Wt1, 128, 128);
    pad_x_kernel<<<(int)((MT * 32 + 255) / 256), 256>>>(x, xpad);

    dim3 ggrid(6, MT / 128);      // n-tiles fastest -> A tile L2-resident
    dim3 rgrid(BB / RR, 2);

    gemm_gx_kernel<32, 3><<<ggrid, 256, smem32>>>(xpad, 32, Wt0, bih00, bih01, gx0);
    rec_kernel<<<rgrid, RBD>>>(gx0, Whh00, bhh00, Whh01, bhh01, out0, nullptr);
    gemm_gx_kernel<128, 2><<<ggrid, 256, smem128>>>(out0, 128, Wt1, bih10, bih11, gx1);
    rec_kernel<<<rgrid, RBD>>>(gx1, Whh10, bhh10, Whh11, bhh11, nullptr, hT);
    head_kernel<<<BB, 128>>>(ln_g, ln_b, W1, b1, W2, b2, out);
}